// round 1
// baseline (speedup 1.0000x reference)
#include <cuda_runtime.h>
#include <math.h>

// Scratch (static __device__ per allocation rules)
__device__ float g_u[4096 * 1024];      // [N][v_word(512) | v_wch(512)]
__device__ float g_wc[1024 * 1024];     // repacked conv_sent_w[:,:,1]
__device__ float g_pmax[32 * 1024];     // per-nblock column max of r
__device__ float g_h[2048];             // tanh(lin1)

// ---------------------------------------------------------------------------
// A: v_word gather (padding_idx=0 -> zero row)
// ---------------------------------------------------------------------------
__global__ void k_word(const int* __restrict__ words, const float* __restrict__ we) {
    int n = blockIdx.x;
    int w = words[n];
    float4 v = make_float4(0.f, 0.f, 0.f, 0.f);
    if (w != 0) v = ((const float4*)(we + (size_t)w * 512))[threadIdx.x];
    ((float4*)(g_u + (size_t)n * 1024))[threadIdx.x] = v;
}

// ---------------------------------------------------------------------------
// B: char conv (512->512, k=3, pad=1, L=32) + maxpool over L -> u right half
// CTA: 4 words x 128 out-channels. K loop: 32 chunks of 16 in-channels.
// Chunk c of 16 channels == chr_emb[char at position c] viewed as [16][32].
// Thread tile: 8 oc x 8 positions. 3-tap via 10-wide register window.
// ---------------------------------------------------------------------------
__global__ __launch_bounds__(256, 2) void k_conv(
    const int* __restrict__ wic, const float* __restrict__ ce,
    const float* __restrict__ cw, const float* __restrict__ cb) {
    __shared__ float Xs[4 * 578];        // [g][17 rows stride][34] (rows 0..15 used, idx0/33 = halo)
    __shared__ float Ws[128 * 49];       // [o][a*3+k], padded row
    __shared__ float red[128 * 17];
    __shared__ int   cs[4 * 32];

    int t   = threadIdx.x;
    int nb  = blockIdx.x * 4;
    int oc0 = blockIdx.y * 128;

    if (t < 128) cs[t] = wic[nb * 32 + t];
    for (int i = t; i < 64; i += 256) {
        int g = i >> 4, a = i & 15;
        Xs[g * 578 + a * 34 + 0]  = 0.f;
        Xs[g * 578 + a * 34 + 33] = 0.f;
    }

    int tx = t & 15, ty = t >> 4;
    int g  = tx >> 2;
    int l0 = (tx & 3) * 8;
    const float* Xg = Xs + g * 578;

    float acc[8][8];
#pragma unroll
    for (int i = 0; i < 8; i++)
#pragma unroll
        for (int j = 0; j < 8; j++) acc[i][j] = 0.f;

    __syncthreads();

    for (int chunk = 0; chunk < 32; chunk++) {
        // load X: 4 words x 512 floats (one char-emb row each)
#pragma unroll
        for (int j = 0; j < 8; j++) {
            int i  = t + j * 256;            // 0..2047
            int gg = i >> 9, d = i & 511;
            int c  = cs[gg * 32 + chunk];
            float v = (c == 0) ? 0.f : ce[c * 512 + d];
            Xs[gg * 578 + (d >> 5) * 34 + 1 + (d & 31)] = v;
        }
        // load W: 128 oc x 16 ic x 3 taps
#pragma unroll
        for (int j = 0; j < 24; j++) {
            int i = t + j * 256;             // 0..6143
            int o = i / 48, r = i - o * 48;
            Ws[o * 49 + r] = cw[(size_t)(oc0 + o) * 1536 + chunk * 48 + r];
        }
        __syncthreads();

#pragma unroll 2
        for (int a = 0; a < 16; a++) {
            float xr[10];
#pragma unroll
            for (int p = 0; p < 10; p++) xr[p] = Xg[a * 34 + l0 + p];  // x pos l0-1..l0+8
#pragma unroll
            for (int k = 0; k < 3; k++) {
#pragma unroll
                for (int oo = 0; oo < 8; oo++) {
                    float w = Ws[(ty * 8 + oo) * 49 + a * 3 + k];
#pragma unroll
                    for (int cc = 0; cc < 8; cc++)
                        acc[oo][cc] = fmaf(w, xr[k + cc], acc[oo][cc]);
                }
            }
        }
        __syncthreads();
    }

    // maxpool over positions: per-thread over 8 cols, then across 4 threads/word
#pragma unroll
    for (int oo = 0; oo < 8; oo++) {
        float m = acc[oo][0];
#pragma unroll
        for (int cc = 1; cc < 8; cc++) m = fmaxf(m, acc[oo][cc]);
        red[(ty * 8 + oo) * 17 + tx] = m;
    }
    __syncthreads();
    for (int i = t; i < 512; i += 256) {
        int gg = i >> 7, o = i & 127;
        const float* rp = red + o * 17 + gg * 4;
        float m = fmaxf(fmaxf(rp[0], rp[1]), fmaxf(rp[2], rp[3]));
        g_u[(size_t)(nb + gg) * 1024 + 512 + oc0 + o] = m + cb[oc0 + o];
    }
}

// ---------------------------------------------------------------------------
// C1: repack conv_sent_w center tap -> dense [1024][1024]
// ---------------------------------------------------------------------------
__global__ void k_repack(const float* __restrict__ ws) {
    int i = blockIdx.x * 256 + threadIdx.x;   // 0..1024*1024-1
    g_wc[i] = ws[(size_t)i * 3 + 1];
}

// ---------------------------------------------------------------------------
// C2: r = u @ Wc^T + b, fused per-CTA column max -> g_pmax[nblk][1024]
// 128n x 128o tile, K=1024 in chunks of 32
// ---------------------------------------------------------------------------
__global__ __launch_bounds__(256, 2) void k_sent(const float* __restrict__ csb) {
    __shared__ float Us[32 * 129];
    __shared__ float Wss[32 * 129];
    __shared__ float red[128 * 17];
    int t  = threadIdx.x;
    int nb = blockIdx.x * 128;
    int o0 = blockIdx.y * 128;
    int tx = t & 15, ty = t >> 4;

    float acc[8][8];
#pragma unroll
    for (int i = 0; i < 8; i++)
#pragma unroll
        for (int j = 0; j < 8; j++) acc[i][j] = 0.f;

    for (int i0 = 0; i0 < 1024; i0 += 32) {
#pragma unroll
        for (int j = 0; j < 16; j++) {
            int i = t + j * 256;              // 0..4095
            int n = i >> 5, k = i & 31;
            Us[k * 129 + n]  = g_u[(size_t)(nb + n) * 1024 + i0 + k];
            Wss[k * 129 + n] = g_wc[(size_t)(o0 + n) * 1024 + i0 + k];
        }
        __syncthreads();
#pragma unroll 4
        for (int k = 0; k < 32; k++) {
            float xv[8], wv[8];
#pragma unroll
            for (int nn = 0; nn < 8; nn++) xv[nn] = Us[k * 129 + tx + nn * 16];
#pragma unroll
            for (int oo = 0; oo < 8; oo++) wv[oo] = Wss[k * 129 + ty * 8 + oo];
#pragma unroll
            for (int oo = 0; oo < 8; oo++)
#pragma unroll
                for (int nn = 0; nn < 8; nn++)
                    acc[oo][nn] = fmaf(wv[oo], xv[nn], acc[oo][nn]);
        }
        __syncthreads();
    }

#pragma unroll
    for (int oo = 0; oo < 8; oo++) {
        float m = acc[oo][0];
#pragma unroll
        for (int nn = 1; nn < 8; nn++) m = fmaxf(m, acc[oo][nn]);
        red[(ty * 8 + oo) * 17 + tx] = m;
    }
    __syncthreads();
    if (t < 128) {
        float m = red[t * 17];
#pragma unroll
        for (int j = 1; j < 16; j++) m = fmaxf(m, red[t * 17 + j]);
        g_pmax[blockIdx.x * 1024 + o0 + t] = m + csb[o0 + t];
    }
}

// ---------------------------------------------------------------------------
// D2: final max over 32 partials (recomputed per block, tiny), then lin1+tanh
// ---------------------------------------------------------------------------
__global__ void k_lin1(const float* __restrict__ w1, const float* __restrict__ b1) {
    __shared__ float rm[1024];
    int t = threadIdx.x;   // 128
    for (int o = t; o < 1024; o += 128) {
        float m = g_pmax[o];
#pragma unroll
        for (int j = 1; j < 32; j++) m = fmaxf(m, g_pmax[j * 1024 + o]);
        rm[o] = m;
    }
    __syncthreads();
    int j = blockIdx.x * 128 + t;          // 0..2047
    float s = b1[j];
    const float* wr = w1 + (size_t)j * 1024;
    for (int i = 0; i < 1024; i++) s = fmaf(rm[i], wr[i], s);
    g_h[j] = tanhf(s);
}

// ---------------------------------------------------------------------------
// D3: out = h @ lin2_w^T + lin2_b  -> [2]
// ---------------------------------------------------------------------------
__global__ void k_lin2(const float* __restrict__ w2, const float* __restrict__ b2,
                       float* __restrict__ out) {
    __shared__ float p0s[256], p1s[256];
    int t = threadIdx.x;
    float p0 = 0.f, p1 = 0.f;
    for (int i = t; i < 2048; i += 256) {
        float h = g_h[i];
        p0 = fmaf(h, w2[i], p0);
        p1 = fmaf(h, w2[2048 + i], p1);
    }
    p0s[t] = p0; p1s[t] = p1;
    __syncthreads();
    for (int s = 128; s > 0; s >>= 1) {
        if (t < s) { p0s[t] += p0s[t + s]; p1s[t] += p1s[t + s]; }
        __syncthreads();
    }
    if (t == 0) { out[0] = p0s[0] + b2[0]; out[1] = p1s[0] + b2[1]; }
}

// ---------------------------------------------------------------------------
extern "C" void kernel_launch(void* const* d_in, const int* in_sizes, int n_in,
                              void* d_out, int out_size) {
    const int*   words = (const int*)d_in[0];
    const int*   wic   = (const int*)d_in[1];
    const float* we    = (const float*)d_in[2];
    const float* ce    = (const float*)d_in[3];
    const float* cw    = (const float*)d_in[4];
    const float* cb    = (const float*)d_in[5];
    const float* ws    = (const float*)d_in[6];
    const float* csb   = (const float*)d_in[7];
    const float* w1    = (const float*)d_in[8];
    const float* b1    = (const float*)d_in[9];
    const float* w2    = (const float*)d_in[10];
    const float* b2    = (const float*)d_in[11];
    float* out = (float*)d_out;

    k_word  <<<4096, 128>>>(words, we);
    k_repack<<<4096, 256>>>(ws);
    k_conv  <<<dim3(1024, 4), 256>>>(wic, ce, cw, cb);
    k_sent  <<<dim3(32, 8), 256>>>(csb);
    k_lin1  <<<16, 128>>>(w1, b1);
    k_lin2  <<<1, 256>>>(w2, b2, out);
}